// round 2
// baseline (speedup 1.0000x reference)
#include <cuda_runtime.h>
#include <math.h>

// ---------------- problem constants ----------------
#define BATCH   64
#define RESO    28
#define NTOK    784            // 28*28
#define DIMC    384
#define CBR     192            // per-branch channels
#define HEADS   8
#define CHH     24             // CBR / HEADS
#define WIN     196            // window tokens
#define GPB     32             // windows*heads per batch per branch
#define HID     1536
#define MTOK    (BATCH*NTOK)   // 50176
#define MGEN    (BATCH*GPB)    // 2048
#define KGEN    392            // WIN*DMIX
#define NGEN    38416          // WIN*WIN

// ---------------- scratch (static device allocations) ----------------
__device__ __align__(16) float g_an[(size_t)MTOK*DIMC];
__device__ __align__(16) float g_wv0[(size_t)MGEN*KGEN];
__device__ __align__(16) float g_wv1[(size_t)MGEN*KGEN];
__device__ __align__(16) float g_logits[(size_t)MGEN*NGEN];
__device__ __align__(16) float g_attn[(size_t)MTOK*DIMC];
__device__ __align__(16) float g_xmid[(size_t)MTOK*DIMC];
__device__ __align__(16) float g_mn[(size_t)MTOK*DIMC];
__device__ __align__(16) float g_h[(size_t)MTOK*HID];

// ---------------- center norm: w*(scale*(x-mean)) + b ----------------
__global__ void knorm(const float* __restrict__ x, const float* __restrict__ w,
                      const float* __restrict__ bb, float* __restrict__ out) {
    int t = blockIdx.x;
    const float* xr = x + (size_t)t * DIMC;
    float* orow = out + (size_t)t * DIMC;
    int tid = threadIdx.x; // 128
    float v0 = xr[tid], v1 = xr[tid + 128], v2 = xr[tid + 256];
    float s = v0 + v1 + v2;
#pragma unroll
    for (int o = 16; o > 0; o >>= 1) s += __shfl_xor_sync(0xffffffffu, s, o);
    __shared__ float red[4];
    if ((tid & 31) == 0) red[tid >> 5] = s;
    __syncthreads();
    float u = (red[0] + red[1] + red[2] + red[3]) * (1.0f / DIMC);
    const float sc = (float)DIMC / (float)(DIMC - 1);
    orow[tid]       = w[tid]       * (sc * (v0 - u)) + bb[tid];
    orow[tid + 128] = w[tid + 128] * (sc * (v1 - u)) + bb[tid + 128];
    orow[tid + 256] = w[tid + 256] * (sc * (v2 - u)) + bb[tid + 256];
}

// ---------------- compress + window rearrange for both branches ----------------
// wv[b*GPB+g][s*2+di] = dot(an[b,n,branch*192 : +192], cw[:, head*2+di]) + cb
__global__ void kcompress(const float* __restrict__ an,
                          const float* __restrict__ c0w, const float* __restrict__ c0b,
                          const float* __restrict__ c1w, const float* __restrict__ c1b,
                          float* __restrict__ wv0, float* __restrict__ wv1) {
    int tok = blockIdx.x;           // b*NTOK + n
    int b = tok / NTOK, n = tok % NTOK;
    __shared__ float xs[DIMC];
    for (int i = threadIdx.x; i < DIMC; i += 32)
        xs[i] = an[(size_t)tok * DIMC + i];
    __syncwarp();
    int tid = threadIdx.x;          // 32 threads
    int branch = tid >> 4;
    int j = tid & 15;               // head*2 + di
    const float* cw  = branch ? c1w : c0w;
    const float* cbv = branch ? c1b : c0b;
    const float* xb = xs + branch * CBR;
    float acc = cbv[j];
#pragma unroll 4
    for (int k = 0; k < CBR; k++) acc = fmaf(xb[k], cw[k * 16 + j], acc);
    int head = j >> 1, di = j & 1;
    int row = n / RESO, col = n % RESO;
    int g, s;
    if (branch == 0) { // H_sp=28, W_sp=7, n1=1, n2=4
        int n2i = col / 7; int h = row; int w = col % 7;
        g = n2i * HEADS + head; s = h * 7 + w;
    } else {           // H_sp=7, W_sp=28, n1=4, n2=1
        int n1i = row / 7; int h = row % 7;
        g = n1i * HEADS + head; s = h * 28 + col;
    }
    float* dst = branch ? wv1 : wv0;
    dst[(size_t)(b * GPB + g) * KGEN + s * 2 + di] = acc;
}

// ---------------- generic tiled SGEMM with fused epilogue ----------------
// C = epi(A(MxK) @ B(KxN) + bias)
// EPI 0: none; 1: exact GELU; 2: out = res + alpha[n]*val
template <int EPI>
__global__ __launch_bounds__(256) void sgemm(
    const float* __restrict__ A, const float* __restrict__ Bm,
    const float* __restrict__ bias, const float* __restrict__ res,
    const float* __restrict__ alpha, float* __restrict__ C,
    int M, int N, int K) {
    __shared__ float As[8][128];
    __shared__ float Bs[8][128];
    int tid = threadIdx.x;
    int row0 = blockIdx.y * 128, col0 = blockIdx.x * 128;
    int tx = tid & 15, ty = tid >> 4;

    int aRow = tid >> 1;
    int aCol = (tid & 1) * 4;
    int bRow = tid >> 5;
    int bCol = (tid & 31) * 4;

    bool aValid = (row0 + aRow) < M;
    bool bValid = (col0 + bCol) < N;   // N % 4 == 0 for all our shapes

    const float* aPtr = A + (size_t)(row0 + aRow) * K + aCol;
    const float* bPtr = Bm + (size_t)bRow * N + col0 + bCol;

    float acc[8][8] = {};
    for (int k0 = 0; k0 < K; k0 += 8) {
        float4 av = aValid ? *(const float4*)aPtr : make_float4(0, 0, 0, 0);
        float4 bv = bValid ? *(const float4*)bPtr : make_float4(0, 0, 0, 0);
        As[aCol + 0][aRow] = av.x; As[aCol + 1][aRow] = av.y;
        As[aCol + 2][aRow] = av.z; As[aCol + 3][aRow] = av.w;
        *(float4*)&Bs[bRow][bCol] = bv;
        __syncthreads();
#pragma unroll
        for (int kk = 0; kk < 8; kk++) {
            float4 a0 = *(const float4*)&As[kk][ty * 8];
            float4 a1 = *(const float4*)&As[kk][ty * 8 + 4];
            float4 b0 = *(const float4*)&Bs[kk][tx * 8];
            float4 b1 = *(const float4*)&Bs[kk][tx * 8 + 4];
            float ar[8] = {a0.x, a0.y, a0.z, a0.w, a1.x, a1.y, a1.z, a1.w};
            float br[8] = {b0.x, b0.y, b0.z, b0.w, b1.x, b1.y, b1.z, b1.w};
#pragma unroll
            for (int i = 0; i < 8; i++)
#pragma unroll
                for (int j = 0; j < 8; j++)
                    acc[i][j] = fmaf(ar[i], br[j], acc[i][j]);
        }
        __syncthreads();
        aPtr += 8;
        bPtr += (size_t)8 * N;
    }
#pragma unroll
    for (int i = 0; i < 8; i++) {
        int r = row0 + ty * 8 + i;
        if (r >= M) continue;
#pragma unroll
        for (int j = 0; j < 8; j++) {
            int c = col0 + tx * 8 + j;
            if (c >= N) continue;
            float v = acc[i][j] + bias[c];
            size_t idx = (size_t)r * N + c;
            if (EPI == 1) v = 0.5f * v * (1.0f + erff(v * 0.70710678118654752f));
            if (EPI == 2) v = res[idx] + alpha[c] * v;
            C[idx] = v;
        }
    }
}

// ---------------- fused softmax(source axis) + V@W + scatter ----------------
// one block per (b, g). logits row (196s x 196t) lives in SMEM.
__global__ __launch_bounds__(256) void kmix(const float* __restrict__ logits,
                                            const float* __restrict__ an,
                                            float* __restrict__ attn, int branch) {
    extern __shared__ float sm[];
    float* p    = sm;                    // 38416 logits -> probabilities*sum
    float* v    = sm + NGEN;             // 24 x 196 values
    float* sInv = sm + NGEN + CHH * WIN; // 196 inverse sums

    int bg = blockIdx.x;
    int b = bg / GPB, g = bg % GPB;
    int head = g % HEADS, wi = g / HEADS; // wi = n2_i (br0) or n1_i (br1)
    int coff = branch * CBR + head * CHH;

    const float4* lrow = (const float4*)(logits + (size_t)bg * NGEN);
    float4* p4 = (float4*)p;
    for (int i = threadIdx.x; i < NGEN / 4; i += blockDim.x) p4[i] = lrow[i];

    for (int i = threadIdx.x; i < CHH * WIN; i += blockDim.x) {
        int ch = i / WIN, s = i % WIN;
        int n;
        if (branch == 0) { int h = s / 7, w = s % 7; n = h * RESO + wi * 7 + w; }
        else             { int h = s / 28, w = s % 28; n = (wi * 7 + h) * RESO + w; }
        v[i] = an[((size_t)b * NTOK + n) * DIMC + coff + ch];
    }
    __syncthreads();

    int t = threadIdx.x;
    if (t < WIN) {
        float mx = -1e30f;
        for (int s = 0; s < WIN; s++) mx = fmaxf(mx, p[s * WIN + t]);
        float sum = 0.0f;
        for (int s = 0; s < WIN; s++) {
            float e = __expf(p[s * WIN + t] - mx);
            p[s * WIN + t] = e;
            sum += e;
        }
        sInv[t] = 1.0f / sum;
    }
    __syncthreads();

    for (int o = threadIdx.x; o < CHH * WIN; o += blockDim.x) {
        int ch = o / WIN, tt = o % WIN;
        float acc = 0.0f;
        const float* vr = v + ch * WIN;
#pragma unroll 4
        for (int s = 0; s < WIN; s++) acc = fmaf(vr[s], p[s * WIN + tt], acc);
        acc *= sInv[tt];
        int n;
        if (branch == 0) { int h = tt / 7, w = tt % 7; n = h * RESO + wi * 7 + w; }
        else             { int h = tt / 28, w = tt % 28; n = (wi * 7 + h) * RESO + w; }
        attn[((size_t)b * NTOK + n) * DIMC + coff + ch] = acc;
    }
}

// ---------------- launch ----------------
extern "C" void kernel_launch(void* const* d_in, const int* in_sizes, int n_in,
                              void* d_out, int out_size) {
    const float* x   = (const float*)d_in[0];
    const float* n1w = (const float*)d_in[1];
    const float* n1b = (const float*)d_in[2];
    const float* n2w = (const float*)d_in[3];
    const float* n2b = (const float*)d_in[4];
    const float* c0w = (const float*)d_in[5];
    const float* c0b = (const float*)d_in[6];
    const float* g0w = (const float*)d_in[7];
    const float* g0b = (const float*)d_in[8];
    const float* c1w = (const float*)d_in[9];
    const float* c1b = (const float*)d_in[10];
    const float* g1w = (const float*)d_in[11];
    const float* g1b = (const float*)d_in[12];
    const float* pw  = (const float*)d_in[13];
    const float* pb  = (const float*)d_in[14];
    const float* f1w = (const float*)d_in[15];
    const float* f1b = (const float*)d_in[16];
    const float* f2w = (const float*)d_in[17];
    const float* f2b = (const float*)d_in[18];
    const float* a1  = (const float*)d_in[19];
    const float* a2  = (const float*)d_in[20];
    float* out = (float*)d_out;

    float *an, *wv0, *wv1, *logits, *attn, *xmid, *mn, *h;
    cudaGetSymbolAddress((void**)&an, g_an);
    cudaGetSymbolAddress((void**)&wv0, g_wv0);
    cudaGetSymbolAddress((void**)&wv1, g_wv1);
    cudaGetSymbolAddress((void**)&logits, g_logits);
    cudaGetSymbolAddress((void**)&attn, g_attn);
    cudaGetSymbolAddress((void**)&xmid, g_xmid);
    cudaGetSymbolAddress((void**)&mn, g_mn);
    cudaGetSymbolAddress((void**)&h, g_h);

    int smix = (NGEN + CHH * WIN + WIN) * sizeof(float); // 173264 B
    cudaFuncSetAttribute(kmix, cudaFuncAttributeMaxDynamicSharedMemorySize, smix);

    // 1. norm1
    knorm<<<MTOK, 128>>>(x, n1w, n1b, an);
    // 2. compress both branches
    kcompress<<<MTOK, 32>>>(an, c0w, c0b, c1w, c1b, wv0, wv1);
    // 3/4. branch 0: logits GEMM + fused softmax/AV/scatter
    dim3 gl((NGEN + 127) / 128, MGEN / 128);
    sgemm<0><<<gl, 256>>>(wv0, g0w, g0b, nullptr, nullptr, logits, MGEN, NGEN, KGEN);
    kmix<<<MGEN, 256, smix>>>(logits, an, attn, 0);
    // 5/6. branch 1 (reuses logits buffer)
    sgemm<0><<<gl, 256>>>(wv1, g1w, g1b, nullptr, nullptr, logits, MGEN, NGEN, KGEN);
    kmix<<<MGEN, 256, smix>>>(logits, an, attn, 1);
    // 7. proj + alpha1 residual
    dim3 gp(DIMC / 128, MTOK / 128);
    sgemm<2><<<gp, 256>>>(attn, pw, pb, x, a1, xmid, MTOK, DIMC, DIMC);
    // 8. norm2
    knorm<<<MTOK, 128>>>(xmid, n2w, n2b, mn);
    // 9. fc1 + GELU
    dim3 gf1(HID / 128, MTOK / 128);
    sgemm<1><<<gf1, 256>>>(mn, f1w, f1b, nullptr, nullptr, h, MTOK, HID, DIMC);
    // 10. fc2 + alpha2 residual -> output
    sgemm<2><<<gp, 256>>>(h, f2w, f2b, xmid, a2, out, MTOK, DIMC, HID);
}

// round 4
// speedup vs baseline: 2.4673x; 2.4673x over previous
#include <cuda_runtime.h>
#include <math.h>
#include <stdint.h>

// ---------------- problem constants ----------------
#define BATCH   64
#define RESO    28
#define NTOK    784
#define DIMC    384
#define CBR     192
#define HEADS   8
#define CHH     24
#define WIN     196
#define GPB     32
#define HID     1536
#define MTOK    (BATCH*NTOK)   // 50176
#define MGEN    (BATCH*GPB)    // 2048
#define KGEN    392
#define KGENP   416
#define NGEN    38416

// ---------------- scratch ----------------
__device__ __align__(16) float g_an[(size_t)MTOK*DIMC];
__device__ __align__(16) float g_wv0[(size_t)MGEN*KGENP];
__device__ __align__(16) float g_wv1[(size_t)MGEN*KGENP];
__device__ __align__(16) float g_logits[(size_t)MGEN*NGEN];
__device__ __align__(16) float g_attn[(size_t)MTOK*DIMC];
__device__ __align__(16) float g_xmid[(size_t)MTOK*DIMC];
__device__ __align__(16) float g_mn[(size_t)MTOK*DIMC];
__device__ __align__(16) float g_h[(size_t)MTOK*HID];

// ---------------- tf32 round-to-nearest-even ----------------
__device__ __forceinline__ float rtf32(float x) {
    unsigned u = __float_as_uint(x);
    u += 0xFFFu + ((u >> 13) & 1u);
    u &= 0xFFFFE000u;
    return __uint_as_float(u);
}
__device__ __forceinline__ uint32_t rtf32b(float x) {
    unsigned u = __float_as_uint(x);
    u += 0xFFFu + ((u >> 13) & 1u);
    return u & 0xFFFFE000u;
}

__device__ __forceinline__ uint32_t smem_u32(const void* p) {
    uint32_t a;
    asm("{ .reg .u64 t; cvta.to.shared.u64 t, %1; cvt.u32.u64 %0, t; }" : "=r"(a) : "l"(p));
    return a;
}
__device__ __forceinline__ void cp16(uint32_t d, const float* s, uint32_t sz) {
    asm volatile("cp.async.cg.shared.global [%0], [%1], 16, %2;" :: "r"(d), "l"(s), "r"(sz));
}
#define CP_COMMIT() asm volatile("cp.async.commit_group;" ::: "memory")
#define CP_WAIT(n)  asm volatile("cp.async.wait_group %0;" :: "n"(n) : "memory")

__device__ __forceinline__ void mma8(float* d, const uint32_t* a, const uint32_t* b) {
    asm volatile(
        "mma.sync.aligned.m16n8k8.row.col.f32.tf32.tf32.f32 "
        "{%0,%1,%2,%3},{%4,%5,%6,%7},{%8,%9},{%0,%1,%2,%3};"
        : "+f"(d[0]), "+f"(d[1]), "+f"(d[2]), "+f"(d[3])
        : "r"(a[0]), "r"(a[1]), "r"(a[2]), "r"(a[3]), "r"(b[0]), "r"(b[1]));
}

// ---------------- center norm ----------------
template <bool RND>
__global__ void knorm(const float* __restrict__ x, const float* __restrict__ w,
                      const float* __restrict__ bb, float* __restrict__ out) {
    int t = blockIdx.x;
    const float* xr = x + (size_t)t * DIMC;
    float* orow = out + (size_t)t * DIMC;
    int tid = threadIdx.x; // 128
    float v0 = xr[tid], v1 = xr[tid + 128], v2 = xr[tid + 256];
    float s = v0 + v1 + v2;
#pragma unroll
    for (int o = 16; o > 0; o >>= 1) s += __shfl_xor_sync(0xffffffffu, s, o);
    __shared__ float red[4];
    if ((tid & 31) == 0) red[tid >> 5] = s;
    __syncthreads();
    float u = (red[0] + red[1] + red[2] + red[3]) * (1.0f / DIMC);
    const float sc = (float)DIMC / (float)(DIMC - 1);
    float o0 = w[tid]       * (sc * (v0 - u)) + bb[tid];
    float o1 = w[tid + 128] * (sc * (v1 - u)) + bb[tid + 128];
    float o2 = w[tid + 256] * (sc * (v2 - u)) + bb[tid + 256];
    orow[tid]       = RND ? rtf32(o0) : o0;
    orow[tid + 128] = RND ? rtf32(o1) : o1;
    orow[tid + 256] = RND ? rtf32(o2) : o2;
}

// ---------------- compress + window rearrange (tf32-rounded output) ----------------
__global__ void kcompress(const float* __restrict__ an,
                          const float* __restrict__ c0w, const float* __restrict__ c0b,
                          const float* __restrict__ c1w, const float* __restrict__ c1b,
                          float* __restrict__ wv0, float* __restrict__ wv1) {
    int tok = blockIdx.x;
    int b = tok / NTOK, n = tok % NTOK;
    __shared__ float xs[DIMC];
    for (int i = threadIdx.x; i < DIMC; i += 32)
        xs[i] = an[(size_t)tok * DIMC + i];
    __syncwarp();
    int tid = threadIdx.x;          // 32
    int branch = tid >> 4;
    int j = tid & 15;
    const float* cw  = branch ? c1w : c0w;
    const float* cbv = branch ? c1b : c0b;
    const float* xb = xs + branch * CBR;
    float acc = cbv[j];
#pragma unroll 4
    for (int k = 0; k < CBR; k++) acc = fmaf(xb[k], cw[k * 16 + j], acc);
    int head = j >> 1, di = j & 1;
    int row = n / RESO, col = n % RESO;
    int g, s;
    if (branch == 0) { int n2i = col / 7; g = n2i * HEADS + head; s = row * 7 + col % 7; }
    else             { int n1i = row / 7; g = n1i * HEADS + head; s = (row % 7) * 28 + col; }
    float* dst = branch ? wv1 : wv0;
    dst[(size_t)(b * GPB + g) * KGENP + s * 2 + di] = rtf32(acc);
}

// zero the K padding of wv rows
__global__ void kpad(float* __restrict__ wv0, float* __restrict__ wv1) {
    int r = blockIdx.x, t = threadIdx.x;
    if (t < KGENP - KGEN) {
        wv0[(size_t)r * KGENP + KGEN + t] = 0.0f;
        wv1[(size_t)r * KGENP + KGEN + t] = 0.0f;
    }
}

// ---------------- tf32 mma.sync GEMM: C(M,NC) = epi(A @ B + bias) ----------------
// A: M x lda row-major (tf32-rounded). B: Kreal x NC row-major fp32 (rounded in-reg).
// Block 128x128, BK=16, 8 warps (2M x 4N), warp 64x32 via m16n8k8.
// EPI 0: none; 1: exact GELU + tf32 round; 2: res + alpha*v.
template <int EPI>
__global__ __launch_bounds__(256) void tgemm(
    const float* __restrict__ A, const float* __restrict__ B,
    const float* __restrict__ bias, const float* __restrict__ res,
    const float* __restrict__ alpha, float* __restrict__ C,
    int lda, int Kreal, int NC) {
    __shared__ float As[2][128][20];
    __shared__ float Bs[2][16][136];

    int tid = threadIdx.x;
    int w = tid >> 5, lane = tid & 31;
    int warpM = w >> 2, warpN = w & 3;
    int lr = lane >> 2, lc = lane & 3;
    int row0 = blockIdx.y * 128, col0 = blockIdx.x * 128;
    const int S = lda / 16;

    float acc[4][4][4];
#pragma unroll
    for (int a = 0; a < 4; a++)
#pragma unroll
        for (int bq = 0; bq < 4; bq++)
#pragma unroll
            for (int cq = 0; cq < 4; cq++) acc[a][bq][cq] = 0.0f;

    auto load_stage = [&](int s, int buf) {
        int s16 = s * 16;
#pragma unroll
        for (int i = 0; i < 2; i++) {
            int idx = tid + i * 256;
            int r = idx >> 2, c = idx & 3;
            cp16(smem_u32(&As[buf][r][c * 4]),
                 A + (size_t)(row0 + r) * lda + s16 + c * 4, 16u);
        }
#pragma unroll
        for (int i = 0; i < 2; i++) {
            int idx = tid + i * 256;
            int k = idx >> 5, c = idx & 31;
            int krow = s16 + k, gc = col0 + c * 4;
            bool val = (krow < Kreal) && (gc < NC);
            const float* sp = val ? (B + (size_t)krow * NC + gc) : B;
            cp16(smem_u32(&Bs[buf][k][c * 4]), sp, val ? 16u : 0u);
        }
    };

    load_stage(0, 0);
    CP_COMMIT();

    for (int s = 0; s < S; s++) {
        int cur = s & 1;
        if (s + 1 < S) {
            load_stage(s + 1, cur ^ 1);
            CP_COMMIT();
            CP_WAIT(1);
        } else {
            CP_WAIT(0);
        }
        __syncthreads();

#pragma unroll
        for (int ks = 0; ks < 2; ks++) {
            uint32_t ar[4][4];
            uint32_t br[4][2];
#pragma unroll
            for (int mt = 0; mt < 4; mt++) {
                int r = warpM * 64 + mt * 16 + lr;
                int kk = ks * 8 + lc;
                ar[mt][0] = __float_as_uint(As[cur][r][kk]);
                ar[mt][1] = __float_as_uint(As[cur][r + 8][kk]);
                ar[mt][2] = __float_as_uint(As[cur][r][kk + 4]);
                ar[mt][3] = __float_as_uint(As[cur][r + 8][kk + 4]);
            }
#pragma unroll
            for (int nt = 0; nt < 4; nt++) {
                int cn = warpN * 32 + nt * 8 + lr;
                int kk = ks * 8 + lc;
                br[nt][0] = rtf32b(Bs[cur][kk][cn]);
                br[nt][1] = rtf32b(Bs[cur][kk + 4][cn]);
            }
#pragma unroll
            for (int mt = 0; mt < 4; mt++)
#pragma unroll
                for (int nt = 0; nt < 4; nt++)
                    mma8(acc[mt][nt], ar[mt], br[nt]);
        }
        __syncthreads();
    }

    // epilogue: direct float2 stores
#pragma unroll
    for (int mt = 0; mt < 4; mt++) {
#pragma unroll
        for (int nt = 0; nt < 4; nt++) {
            int cbase = col0 + warpN * 32 + nt * 8 + lc * 2;
            if (cbase >= NC) continue;
            float bi0 = bias[cbase], bi1 = bias[cbase + 1];
            float al0 = 0.f, al1 = 0.f;
            if (EPI == 2) { al0 = alpha[cbase]; al1 = alpha[cbase + 1]; }
#pragma unroll
            for (int hh = 0; hh < 2; hh++) {
                int r = row0 + warpM * 64 + mt * 16 + lr + hh * 8;
                float v0 = acc[mt][nt][hh * 2]     + bi0;
                float v1 = acc[mt][nt][hh * 2 + 1] + bi1;
                size_t idx = (size_t)r * NC + cbase;
                if (EPI == 1) {
                    v0 = rtf32(0.5f * v0 * (1.0f + erff(v0 * 0.70710678118654752f)));
                    v1 = rtf32(0.5f * v1 * (1.0f + erff(v1 * 0.70710678118654752f)));
                }
                if (EPI == 2) {
                    float2 rr = *(const float2*)(res + idx);
                    v0 = rr.x + al0 * v0;
                    v1 = rr.y + al1 * v1;
                }
                float2 o = make_float2(v0, v1);
                *(float2*)(C + idx) = o;
            }
        }
    }
}

// ---------------- fused softmax + V@W + scatter ----------------
__global__ __launch_bounds__(256) void kmix(const float* __restrict__ logits,
                                            const float* __restrict__ an,
                                            float* __restrict__ attn, int branch) {
    extern __shared__ float sm[];
    float* p    = sm;
    float* v    = sm + NGEN;
    float* sInv = sm + NGEN + CHH * WIN;

    int bg = blockIdx.x;
    int b = bg / GPB, g = bg % GPB;
    int head = g % HEADS, wi = g / HEADS;
    int coff = branch * CBR + head * CHH;

    const float4* lrow = (const float4*)(logits + (size_t)bg * NGEN);
    float4* p4 = (float4*)p;
    for (int i = threadIdx.x; i < NGEN / 4; i += blockDim.x) p4[i] = lrow[i];

    for (int i = threadIdx.x; i < CHH * WIN; i += blockDim.x) {
        int ch = i / WIN, s = i % WIN;
        int n;
        if (branch == 0) { int h = s / 7, ww = s % 7; n = h * RESO + wi * 7 + ww; }
        else             { int h = s / 28, ww = s % 28; n = (wi * 7 + h) * RESO + ww; }
        v[i] = an[((size_t)b * NTOK + n) * DIMC + coff + ch];
    }
    __syncthreads();

    int t = threadIdx.x;
    if (t < WIN) {
        float mx = -1e30f;
        for (int s = 0; s < WIN; s++) mx = fmaxf(mx, p[s * WIN + t]);
        float sum = 0.0f;
        for (int s = 0; s < WIN; s++) {
            float e = __expf(p[s * WIN + t] - mx);
            p[s * WIN + t] = e;
            sum += e;
        }
        sInv[t] = 1.0f / sum;
    }
    __syncthreads();

    for (int o = threadIdx.x; o < CHH * (WIN / 4); o += blockDim.x) {
        int ch = o / (WIN / 4), tt = (o % (WIN / 4)) * 4;
        float4 acc = make_float4(0.f, 0.f, 0.f, 0.f);
        const float* vr = v + ch * WIN;
#pragma unroll 2
        for (int s = 0; s < WIN; s++) {
            float vv = vr[s];
            float4 pp = *(const float4*)&p[s * WIN + tt];
            acc.x = fmaf(vv, pp.x, acc.x);
            acc.y = fmaf(vv, pp.y, acc.y);
            acc.z = fmaf(vv, pp.z, acc.z);
            acc.w = fmaf(vv, pp.w, acc.w);
        }
        float r4[4] = {acc.x * sInv[tt], acc.y * sInv[tt + 1],
                       acc.z * sInv[tt + 2], acc.w * sInv[tt + 3]};
#pragma unroll
        for (int q = 0; q < 4; q++) {
            int ttq = tt + q, n;
            if (branch == 0) { int h = ttq / 7, ww = ttq % 7; n = h * RESO + wi * 7 + ww; }
            else             { int h = ttq / 28, ww = ttq % 28; n = (wi * 7 + h) * RESO + ww; }
            attn[((size_t)b * NTOK + n) * DIMC + coff + ch] = rtf32(r4[q]);
        }
    }
}

// ---------------- launch ----------------
extern "C" void kernel_launch(void* const* d_in, const int* in_sizes, int n_in,
                              void* d_out, int out_size) {
    const float* x   = (const float*)d_in[0];
    const float* n1w = (const float*)d_in[1];
    const float* n1b = (const float*)d_in[2];
    const float* n2w = (const float*)d_in[3];
    const float* n2b = (const float*)d_in[4];
    const float* c0w = (const float*)d_in[5];
    const float* c0b = (const float*)d_in[6];
    const float* g0w = (const float*)d_in[7];
    const float* g0b = (const float*)d_in[8];
    const float* c1w = (const float*)d_in[9];
    const float* c1b = (const float*)d_in[10];
    const float* g1w = (const float*)d_in[11];
    const float* g1b = (const float*)d_in[12];
    const float* pw  = (const float*)d_in[13];
    const float* pb  = (const float*)d_in[14];
    const float* f1w = (const float*)d_in[15];
    const float* f1b = (const float*)d_in[16];
    const float* f2w = (const float*)d_in[17];
    const float* f2b = (const float*)d_in[18];
    const float* a1  = (const float*)d_in[19];
    const float* a2  = (const float*)d_in[20];
    float* out = (float*)d_out;

    float *an, *wv0, *wv1, *logits, *attn, *xmid, *mn, *h;
    cudaGetSymbolAddress((void**)&an, g_an);
    cudaGetSymbolAddress((void**)&wv0, g_wv0);
    cudaGetSymbolAddress((void**)&wv1, g_wv1);
    cudaGetSymbolAddress((void**)&logits, g_logits);
    cudaGetSymbolAddress((void**)&attn, g_attn);
    cudaGetSymbolAddress((void**)&xmid, g_xmid);
    cudaGetSymbolAddress((void**)&mn, g_mn);
    cudaGetSymbolAddress((void**)&h, g_h);

    int smix = (NGEN + CHH * WIN + WIN) * sizeof(float);
    cudaFuncSetAttribute(kmix, cudaFuncAttributeMaxDynamicSharedMemorySize, smix);

    // norm1 (fp32 out: feeds kcompress + kmix values)
    knorm<false><<<MTOK, 128>>>(x, n1w, n1b, an);
    // compress (tf32-rounds wv) + zero K pad
    kcompress<<<MTOK, 32>>>(an, c0w, c0b, c1w, c1b, wv0, wv1);
    kpad<<<MGEN, 32>>>(wv0, wv1);

    // branch 0: logits GEMM (2048 x 38416, K=392 pad 416) + mix
    dim3 gl((NGEN + 127) / 128, MGEN / 128);
    tgemm<0><<<gl, 256>>>(wv0, g0w, g0b, nullptr, nullptr, logits, KGENP, KGEN, NGEN);
    kmix<<<MGEN, 256, smix>>>(logits, an, attn, 0);
    // branch 1
    tgemm<0><<<gl, 256>>>(wv1, g1w, g1b, nullptr, nullptr, logits, KGENP, KGEN, NGEN);
    kmix<<<MGEN, 256, smix>>>(logits, an, attn, 1);

    // proj + alpha1 residual
    dim3 gp(DIMC / 128, MTOK / 128);
    tgemm<2><<<gp, 256>>>(attn, pw, pb, x, a1, xmid, DIMC, DIMC, DIMC);
    // norm2 (tf32-rounds mn: A of fc1)
    knorm<true><<<MTOK, 128>>>(xmid, n2w, n2b, mn);
    // fc1 + GELU (tf32-rounds h: A of fc2)
    dim3 gf1(HID / 128, MTOK / 128);
    tgemm<1><<<gf1, 256>>>(mn, f1w, f1b, nullptr, nullptr, h, DIMC, DIMC, HID);
    // fc2 + alpha2 residual -> out
    tgemm<2><<<gp, 256>>>(h, f2w, f2b, xmid, a2, out, HID, HID, DIMC);
}

// round 5
// speedup vs baseline: 4.3183x; 1.7502x over previous
#include <cuda_runtime.h>
#include <cuda_bf16.h>
#include <math.h>
#include <stdint.h>

// ---------------- problem constants ----------------
#define BATCH   64
#define RESO    28
#define NTOK    784
#define DIMC    384
#define CBR     192
#define HEADS   8
#define CHH     24
#define WIN     196
#define GPB     32
#define HID     1536
#define MTOK    (BATCH*NTOK)   // 50176
#define MGEN    (BATCH*GPB)    // 2048
#define KGEN    392
#define KGENP   416
#define NGEN    38416

typedef __nv_bfloat16 bf16;
typedef __nv_bfloat162 bf162;

// ---------------- scratch ----------------
__device__ __align__(16) float g_an[(size_t)MTOK*DIMC];
__device__ __align__(16) bf16  g_wv0[(size_t)MGEN*KGENP];
__device__ __align__(16) bf16  g_wv1[(size_t)MGEN*KGENP];
__device__ __align__(16) bf16  g_logits[(size_t)MGEN*NGEN];
__device__ __align__(16) bf16  g_attn[(size_t)MTOK*DIMC];
__device__ __align__(16) float g_xmid[(size_t)MTOK*DIMC];
__device__ __align__(16) bf16  g_mn[(size_t)MTOK*DIMC];
__device__ __align__(16) bf16  g_h[(size_t)MTOK*HID];
// bf16 weights
__device__ __align__(16) bf16  g_bw0[(size_t)KGEN*NGEN];
__device__ __align__(16) bf16  g_bw1[(size_t)KGEN*NGEN];
__device__ __align__(16) bf16  g_bpw[(size_t)DIMC*DIMC];
__device__ __align__(16) bf16  g_bf1[(size_t)DIMC*HID];
__device__ __align__(16) bf16  g_bf2[(size_t)HID*DIMC];

// ---------------- helpers ----------------
__device__ __forceinline__ uint32_t smem_u32(const void* p) {
    uint32_t a;
    asm("{ .reg .u64 t; cvta.to.shared.u64 t, %1; cvt.u32.u64 %0, t; }" : "=r"(a) : "l"(p));
    return a;
}
__device__ __forceinline__ void cp16(uint32_t d, const void* s, uint32_t sz) {
    asm volatile("cp.async.cg.shared.global [%0], [%1], 16, %2;" :: "r"(d), "l"(s), "r"(sz));
}
#define CP_COMMIT() asm volatile("cp.async.commit_group;" ::: "memory")
#define CP_WAIT(n)  asm volatile("cp.async.wait_group %0;" :: "n"(n) : "memory")

__device__ __forceinline__ void mma16(float* d, const uint32_t* a, const uint32_t* b) {
    asm volatile(
        "mma.sync.aligned.m16n8k16.row.col.f32.bf16.bf16.f32 "
        "{%0,%1,%2,%3},{%4,%5,%6,%7},{%8,%9},{%0,%1,%2,%3};"
        : "+f"(d[0]), "+f"(d[1]), "+f"(d[2]), "+f"(d[3])
        : "r"(a[0]), "r"(a[1]), "r"(a[2]), "r"(a[3]), "r"(b[0]), "r"(b[1]));
}
__device__ __forceinline__ void ldsm4(uint32_t* r, uint32_t addr) {
    asm volatile("ldmatrix.sync.aligned.m8n8.x4.shared.b16 {%0,%1,%2,%3}, [%4];"
        : "=r"(r[0]), "=r"(r[1]), "=r"(r[2]), "=r"(r[3]) : "r"(addr));
}
__device__ __forceinline__ void ldsm4t(uint32_t* r, uint32_t addr) {
    asm volatile("ldmatrix.sync.aligned.m8n8.x4.trans.shared.b16 {%0,%1,%2,%3}, [%4];"
        : "=r"(r[0]), "=r"(r[1]), "=r"(r[2]), "=r"(r[3]) : "r"(addr));
}

template <typename T>
__device__ __forceinline__ void st2(T* C, size_t idx, float v0, float v1);
template <>
__device__ __forceinline__ void st2<float>(float* C, size_t idx, float v0, float v1) {
    *(float2*)(C + idx) = make_float2(v0, v1);
}
template <>
__device__ __forceinline__ void st2<bf16>(bf16* C, size_t idx, float v0, float v1) {
    *(bf162*)(C + idx) = __floats2bfloat162_rn(v0, v1);
}

// ---------------- fp32 -> bf16 weight convert ----------------
__global__ void kcvt(const float* __restrict__ s, bf16* __restrict__ d, int n4) {
    int i = blockIdx.x * blockDim.x + threadIdx.x;
    if (i < n4) {
        float4 f = ((const float4*)s)[i];
        bf162* dd = (bf162*)d;
        dd[i * 2]     = __floats2bfloat162_rn(f.x, f.y);
        dd[i * 2 + 1] = __floats2bfloat162_rn(f.z, f.w);
    }
}

// ---------------- center norm ----------------
template <typename OUTT>
__global__ void knorm(const float* __restrict__ x, const float* __restrict__ w,
                      const float* __restrict__ bb, OUTT* __restrict__ out) {
    int t = blockIdx.x;
    const float* xr = x + (size_t)t * DIMC;
    OUTT* orow = out + (size_t)t * DIMC;
    int tid = threadIdx.x; // 128
    float v0 = xr[tid], v1 = xr[tid + 128], v2 = xr[tid + 256];
    float s = v0 + v1 + v2;
#pragma unroll
    for (int o = 16; o > 0; o >>= 1) s += __shfl_xor_sync(0xffffffffu, s, o);
    __shared__ float red[4];
    if ((tid & 31) == 0) red[tid >> 5] = s;
    __syncthreads();
    float u = (red[0] + red[1] + red[2] + red[3]) * (1.0f / DIMC);
    const float sc = (float)DIMC / (float)(DIMC - 1);
    orow[tid]       = (OUTT)(w[tid]       * (sc * (v0 - u)) + bb[tid]);
    orow[tid + 128] = (OUTT)(w[tid + 128] * (sc * (v1 - u)) + bb[tid + 128]);
    orow[tid + 256] = (OUTT)(w[tid + 256] * (sc * (v2 - u)) + bb[tid + 256]);
}

// ---------------- compress + window rearrange (bf16 out) ----------------
__global__ void kcompress(const float* __restrict__ an,
                          const float* __restrict__ c0w, const float* __restrict__ c0b,
                          const float* __restrict__ c1w, const float* __restrict__ c1b,
                          bf16* __restrict__ wv0, bf16* __restrict__ wv1) {
    int tok = blockIdx.x;
    int b = tok / NTOK, n = tok % NTOK;
    __shared__ float xs[DIMC];
    for (int i = threadIdx.x; i < DIMC; i += 32)
        xs[i] = an[(size_t)tok * DIMC + i];
    __syncwarp();
    int tid = threadIdx.x;          // 32
    int branch = tid >> 4;
    int j = tid & 15;
    const float* cw  = branch ? c1w : c0w;
    const float* cbv = branch ? c1b : c0b;
    const float* xb = xs + branch * CBR;
    float acc = cbv[j];
#pragma unroll 4
    for (int k = 0; k < CBR; k++) acc = fmaf(xb[k], cw[k * 16 + j], acc);
    int head = j >> 1, di = j & 1;
    int row = n / RESO, col = n % RESO;
    int g, s;
    if (branch == 0) { int n2i = col / 7; g = n2i * HEADS + head; s = row * 7 + col % 7; }
    else             { int n1i = row / 7; g = n1i * HEADS + head; s = (row % 7) * 28 + col; }
    bf16* dst = branch ? wv1 : wv0;
    dst[(size_t)(b * GPB + g) * KGENP + s * 2 + di] = __float2bfloat16(acc);
}

__global__ void kpad(bf16* __restrict__ wv0, bf16* __restrict__ wv1) {
    int r = blockIdx.x, t = threadIdx.x;
    if (t < KGENP - KGEN) {
        wv0[(size_t)r * KGENP + KGEN + t] = __float2bfloat16(0.0f);
        wv1[(size_t)r * KGENP + KGEN + t] = __float2bfloat16(0.0f);
    }
}

// ---------------- bf16 mma.sync GEMM: C = epi(A @ B + bias) ----------------
// A: M x lda row-major bf16. B: Kreal x NC row-major bf16.
// Block 128x128, BK=32, 8 warps (2M x 4N), warp 64x32 via m16n8k16 + ldmatrix.
// EPI 0: none; 1: exact GELU; 2: res + alpha*v.
template <int EPI, typename OUTT>
__global__ __launch_bounds__(256, 2) void tgemm(
    const bf16* __restrict__ A, const bf16* __restrict__ B,
    const float* __restrict__ bias, const float* __restrict__ res,
    const float* __restrict__ alpha, OUTT* __restrict__ C,
    int lda, int Kreal, int NC) {
    __shared__ bf16 As[2][128][40];
    __shared__ bf16 Bs[2][32][136];

    int tid = threadIdx.x;
    int w = tid >> 5, lane = tid & 31;
    int warpM = w >> 2, warpN = w & 3;
    int lr = lane >> 2, lc = lane & 3;
    int row0 = blockIdx.y * 128, col0 = blockIdx.x * 128;
    const int S = lda / 32;

    float acc[4][4][4];
#pragma unroll
    for (int a = 0; a < 4; a++)
#pragma unroll
        for (int bq = 0; bq < 4; bq++)
#pragma unroll
            for (int cq = 0; cq < 4; cq++) acc[a][bq][cq] = 0.0f;

    auto load_stage = [&](int s, int buf) {
        int s32 = s * 32;
#pragma unroll
        for (int i = 0; i < 2; i++) {
            int idx = tid + i * 256;         // 512 chunks of 16B
            int r = idx >> 2, c = idx & 3;   // 4 chunks per row (32 bf16)
            cp16(smem_u32(&As[buf][r][c * 8]),
                 A + (size_t)(row0 + r) * lda + s32 + c * 8, 16u);
        }
#pragma unroll
        for (int i = 0; i < 2; i++) {
            int idx = tid + i * 256;         // 512 chunks
            int k = idx >> 4, c = idx & 15;  // 16 chunks per k-row (128 bf16)
            int krow = s32 + k, gc = col0 + c * 8;
            bool val = (krow < Kreal) && (gc < NC);
            const bf16* sp = val ? (B + (size_t)krow * NC + gc) : B;
            cp16(smem_u32(&Bs[buf][k][c * 8]), sp, val ? 16u : 0u);
        }
    };

    load_stage(0, 0);
    CP_COMMIT();

    for (int s = 0; s < S; s++) {
        int cur = s & 1;
        if (s + 1 < S) {
            load_stage(s + 1, cur ^ 1);
            CP_COMMIT();
            CP_WAIT(1);
        } else {
            CP_WAIT(0);
        }
        __syncthreads();

#pragma unroll
        for (int ks = 0; ks < 2; ks++) {
            uint32_t ar[4][4];
            uint32_t br[4][2];
            int m = lane >> 3;                 // matrix index 0..3
            int rA8 = (m & 1) * 8 + (lane & 7);
            int cA = ks * 16 + (m >> 1) * 8;
#pragma unroll
            for (int mt = 0; mt < 4; mt++)
                ldsm4(ar[mt], smem_u32(&As[cur][warpM * 64 + mt * 16 + rA8][cA]));
            int kB = ks * 16 + ((lane >> 3) & 1) * 8 + (lane & 7);
            int nB8 = (lane >> 4) * 8;
#pragma unroll
            for (int np = 0; np < 2; np++) {
                uint32_t rr[4];
                ldsm4t(rr, smem_u32(&Bs[cur][kB][warpN * 32 + np * 16 + nB8]));
                br[np * 2][0] = rr[0]; br[np * 2][1] = rr[1];
                br[np * 2 + 1][0] = rr[2]; br[np * 2 + 1][1] = rr[3];
            }
#pragma unroll
            for (int mt = 0; mt < 4; mt++)
#pragma unroll
                for (int nt = 0; nt < 4; nt++)
                    mma16(acc[mt][nt], ar[mt], br[nt]);
        }
        __syncthreads();
    }

    // epilogue
#pragma unroll
    for (int mt = 0; mt < 4; mt++) {
#pragma unroll
        for (int nt = 0; nt < 4; nt++) {
            int cbase = col0 + warpN * 32 + nt * 8 + lc * 2;
            if (cbase >= NC) continue;
            float bi0 = bias[cbase], bi1 = bias[cbase + 1];
            float al0 = 0.f, al1 = 0.f;
            if (EPI == 2) { al0 = alpha[cbase]; al1 = alpha[cbase + 1]; }
#pragma unroll
            for (int hh = 0; hh < 2; hh++) {
                int r = row0 + warpM * 64 + mt * 16 + lr + hh * 8;
                float v0 = acc[mt][nt][hh * 2]     + bi0;
                float v1 = acc[mt][nt][hh * 2 + 1] + bi1;
                size_t idx = (size_t)r * NC + cbase;
                if (EPI == 1) {
                    v0 = 0.5f * v0 * (1.0f + erff(v0 * 0.70710678118654752f));
                    v1 = 0.5f * v1 * (1.0f + erff(v1 * 0.70710678118654752f));
                }
                if (EPI == 2) {
                    float2 rr = *(const float2*)(res + idx);
                    v0 = rr.x + al0 * v0;
                    v1 = rr.y + al1 * v1;
                }
                st2<OUTT>(C, idx, v0, v1);
            }
        }
    }
}

// ---------------- fused softmax + V@W + scatter (bf16 logits) ----------------
__global__ __launch_bounds__(384) void kmix(const bf16* __restrict__ logits,
                                            const float* __restrict__ an,
                                            bf16* __restrict__ attn, int branch) {
    extern __shared__ char smbase[];
    bf16* p     = (bf16*)smbase;                         // 38416 bf16
    float* v    = (float*)(smbase + NGEN * 2);           // 24 x 196 f32
    float* sInv = v + CHH * WIN;                         // 196 f32

    int bg = blockIdx.x;
    int b = bg / GPB, g = bg % GPB;
    int head = g % HEADS, wi = g / HEADS;
    int coff = branch * CBR + head * CHH;
    int tid = threadIdx.x;

    const uint4* lrow = (const uint4*)(logits + (size_t)bg * NGEN);
    uint4* p16 = (uint4*)p;
    for (int i = tid; i < NGEN / 8; i += 384) p16[i] = lrow[i];

    for (int i = tid; i < CHH * WIN; i += 384) {
        int ch = i / WIN, s = i % WIN;
        int n;
        if (branch == 0) { int h = s / 7, ww = s % 7; n = h * RESO + wi * 7 + ww; }
        else             { int h = s / 28, ww = s % 28; n = (wi * 7 + h) * RESO + ww; }
        v[i] = an[((size_t)b * NTOK + n) * DIMC + coff + ch];
    }
    __syncthreads();

    if (tid < WIN) {
        float mx = -1e30f;
        for (int s = 0; s < WIN; s++)
            mx = fmaxf(mx, __bfloat162float(p[s * WIN + tid]));
        float sum = 0.0f;
        for (int s = 0; s < WIN; s++) {
            float e = __expf(__bfloat162float(p[s * WIN + tid]) - mx);
            bf16 eb = __float2bfloat16(e);
            p[s * WIN + tid] = eb;
            sum += __bfloat162float(eb);
        }
        sInv[tid] = 1.0f / sum;
    }
    __syncthreads();

    // AV: unit = 4 channels x 4 target tokens; 6*49 = 294 units
    if (tid < (CHH / 4) * (WIN / 4)) {
        int chb = tid / (WIN / 4), ttb = tid % (WIN / 4);
        int tt = ttb * 4;
        float a[4][4];
#pragma unroll
        for (int q = 0; q < 4; q++)
#pragma unroll
            for (int j = 0; j < 4; j++) a[q][j] = 0.0f;
        const float* v0r = v + (chb * 4 + 0) * WIN;
        const float* v1r = v + (chb * 4 + 1) * WIN;
        const float* v2r = v + (chb * 4 + 2) * WIN;
        const float* v3r = v + (chb * 4 + 3) * WIN;
        for (int s = 0; s < WIN; s++) {
            uint2 pp = *(const uint2*)(p + s * WIN + tt);
            float2 f0 = __bfloat1622float2(*(const bf162*)&pp.x);
            float2 f1 = __bfloat1622float2(*(const bf162*)&pp.y);
            float pv[4] = {f0.x, f0.y, f1.x, f1.y};
            float vv[4] = {v0r[s], v1r[s], v2r[s], v3r[s]};
#pragma unroll
            for (int q = 0; q < 4; q++)
#pragma unroll
                for (int j = 0; j < 4; j++)
                    a[q][j] = fmaf(vv[q], pv[j], a[q][j]);
        }
#pragma unroll
        for (int j = 0; j < 4; j++) {
            int ttq = tt + j, n;
            if (branch == 0) { int h = ttq / 7, ww = ttq % 7; n = h * RESO + wi * 7 + ww; }
            else             { int h = ttq / 28, ww = ttq % 28; n = (wi * 7 + h) * RESO + ww; }
            float si = sInv[ttq];
            size_t base = ((size_t)b * NTOK + n) * DIMC + coff + chb * 4;
#pragma unroll
            for (int q = 0; q < 4; q++)
                attn[base + q] = __float2bfloat16(a[q][j] * si);
        }
    }
}

// ---------------- launch ----------------
extern "C" void kernel_launch(void* const* d_in, const int* in_sizes, int n_in,
                              void* d_out, int out_size) {
    const float* x   = (const float*)d_in[0];
    const float* n1w = (const float*)d_in[1];
    const float* n1b = (const float*)d_in[2];
    const float* n2w = (const float*)d_in[3];
    const float* n2b = (const float*)d_in[4];
    const float* c0w = (const float*)d_in[5];
    const float* c0b = (const float*)d_in[6];
    const float* g0w = (const float*)d_in[7];
    const float* g0b = (const float*)d_in[8];
    const float* c1w = (const float*)d_in[9];
    const float* c1b = (const float*)d_in[10];
    const float* g1w = (const float*)d_in[11];
    const float* g1b = (const float*)d_in[12];
    const float* pw  = (const float*)d_in[13];
    const float* pb  = (const float*)d_in[14];
    const float* f1w = (const float*)d_in[15];
    const float* f1b = (const float*)d_in[16];
    const float* f2w = (const float*)d_in[17];
    const float* f2b = (const float*)d_in[18];
    const float* a1  = (const float*)d_in[19];
    const float* a2  = (const float*)d_in[20];
    float* out = (float*)d_out;

    float *an, *xmid;
    bf16 *wv0, *wv1, *logits, *attn, *mn, *h, *bw0, *bw1, *bpw, *bf1, *bf2;
    cudaGetSymbolAddress((void**)&an, g_an);
    cudaGetSymbolAddress((void**)&wv0, g_wv0);
    cudaGetSymbolAddress((void**)&wv1, g_wv1);
    cudaGetSymbolAddress((void**)&logits, g_logits);
    cudaGetSymbolAddress((void**)&attn, g_attn);
    cudaGetSymbolAddress((void**)&xmid, g_xmid);
    cudaGetSymbolAddress((void**)&mn, g_mn);
    cudaGetSymbolAddress((void**)&h, g_h);
    cudaGetSymbolAddress((void**)&bw0, g_bw0);
    cudaGetSymbolAddress((void**)&bw1, g_bw1);
    cudaGetSymbolAddress((void**)&bpw, g_bpw);
    cudaGetSymbolAddress((void**)&bf1, g_bf1);
    cudaGetSymbolAddress((void**)&bf2, g_bf2);

    int smix = NGEN * 2 + (CHH * WIN + WIN) * 4; // 96432 B
    cudaFuncSetAttribute(kmix, cudaFuncAttributeMaxDynamicSharedMemorySize, smix);

    // weight conversions (independent)
    int n4;
    n4 = KGEN * NGEN / 4; kcvt<<<(n4 + 255) / 256, 256>>>(g0w, bw0, n4);
    n4 = KGEN * NGEN / 4; kcvt<<<(n4 + 255) / 256, 256>>>(g1w, bw1, n4);
    n4 = DIMC * DIMC / 4; kcvt<<<(n4 + 255) / 256, 256>>>(pw, bpw, n4);
    n4 = DIMC * HID / 4;  kcvt<<<(n4 + 255) / 256, 256>>>(f1w, bf1, n4);
    n4 = HID * DIMC / 4;  kcvt<<<(n4 + 255) / 256, 256>>>(f2w, bf2, n4);

    // norm1 (fp32: feeds kcompress + kmix v-gather)
    knorm<float><<<MTOK, 128>>>(x, n1w, n1b, an);
    // compress (bf16 wv) + zero pad
    kcompress<<<MTOK, 32>>>(an, c0w, c0b, c1w, c1b, wv0, wv1);
    kpad<<<MGEN, 32>>>(wv0, wv1);

    // branch 0: logits GEMM (bf16 out) + mix
    dim3 gl((NGEN + 127) / 128, MGEN / 128);
    tgemm<0, bf16><<<gl, 256>>>(wv0, bw0, g0b, nullptr, nullptr, logits, KGENP, KGEN, NGEN);
    kmix<<<MGEN, 384, smix>>>(logits, an, attn, 0);
    // branch 1
    tgemm<0, bf16><<<gl, 256>>>(wv1, bw1, g1b, nullptr, nullptr, logits, KGENP, KGEN, NGEN);
    kmix<<<MGEN, 384, smix>>>(logits, an, attn, 1);

    // proj + alpha1 residual (fp32 out)
    dim3 gp(DIMC / 128, MTOK / 128);
    tgemm<2, float><<<gp, 256>>>(attn, bpw, pb, x, a1, xmid, DIMC, DIMC, DIMC);
    // norm2 (bf16 out: A of fc1)
    knorm<bf16><<<MTOK, 128>>>(xmid, n2w, n2b, mn);
    // fc1 + GELU (bf16 out: A of fc2)
    dim3 gf1(HID / 128, MTOK / 128);
    tgemm<1, bf16><<<gf1, 256>>>(mn, bf1, f1b, nullptr, nullptr, h, DIMC, DIMC, HID);
    // fc2 + alpha2 residual -> out (fp32)
    tgemm<2, float><<<gp, 256>>>(h, bf2, f2b, xmid, a2, out, HID, HID, DIMC);
}